// round 5
// baseline (speedup 1.0000x reference)
#include <cuda_runtime.h>

#define D_FEAT   128
#define N_CLASS  10
#define PSTRIDE  12
#define MAX_NODES 100000
#define TILE     256
#define CHUNK    32            // cols per staging chunk
#define SROW     36            // padded smem row stride in words (conflict-free)

__device__ __align__(16) float g_P[MAX_NODES * PSTRIDE];
__device__ __align__(16) float g_Q[MAX_NODES * PSTRIDE];

// packed f32x2 fma: acc += a * b (two lanes)
#define FFMA2(acc, a, b) \
    asm("fma.rn.f32x2 %0, %1, %2, %0;" : "+l"(acc) : "l"(a), "l"(b))

__device__ __forceinline__ float unpack_sum(unsigned long long p) {
    return __uint_as_float((unsigned)(p & 0xffffffffu)) +
           __uint_as_float((unsigned)(p >> 32));
}

// ---------------------------------------------------------------------------
// Kernel 1: node projection, staged + packed.
//   P[n] = h[n] @ W[:,0:128]^T + b ;  Q[n] = h[n] @ W[:,128:256]^T
// ---------------------------------------------------------------------------
__global__ void node_project_kernel(const float* __restrict__ h,
                                    const float* __restrict__ W,
                                    const float* __restrict__ b,
                                    int n_nodes) {
    __shared__ float sWU[N_CLASS * 128];
    __shared__ float sWV[N_CLASS * 128];
    __shared__ __align__(16) float sbuf[TILE * SROW];
    __shared__ float bsh[N_CLASS];

    int tid = threadIdx.x;
    for (int i = tid; i < N_CLASS * 128; i += TILE) {
        int c = i >> 7, j = i & 127;
        sWU[i] = W[c * 384 + j];
        sWV[i] = W[c * 384 + 128 + j];
    }
    if (tid < N_CLASS) bsh[tid] = b[tid];

    int n0 = blockIdx.x * TILE;
    bool full = (n0 + TILE <= n_nodes);
    const float4* hv = (const float4*)h;

    unsigned long long accU[N_CLASS], accV[N_CLASS];
#pragma unroll
    for (int c = 0; c < N_CLASS; c++) { accU[c] = 0ull; accV[c] = 0ull; }

    for (int chunk = 0; chunk < 4; chunk++) {
        __syncthreads();
        // coalesced load: 2048 float4, 8 per thread
#pragma unroll
        for (int k = 0; k < 8; k++) {
            int li = tid + k * TILE;
            int r = li >> 3, cc = li & 7;
            float4 v;
            if (full || (n0 + r) < n_nodes)
                v = hv[(size_t)(n0 + r) * 32 + chunk * 8 + cc];
            else
                v = make_float4(0.f, 0.f, 0.f, 0.f);
            *(float4*)(sbuf + r * SROW + cc * 4) = v;
        }
        __syncthreads();

        const ulonglong2* vt = (const ulonglong2*)(sbuf + tid * SROW);
        const ulonglong2* WU = (const ulonglong2*)sWU;
        const ulonglong2* WV = (const ulonglong2*)sWV;
#pragma unroll
        for (int i = 0; i < 8; i++) {
            ulonglong2 v = vt[i];
#pragma unroll
            for (int c = 0; c < N_CLASS; c++) {
                ulonglong2 wu = WU[c * 32 + chunk * 8 + i];
                ulonglong2 wv = WV[c * 32 + chunk * 8 + i];
                FFMA2(accU[c], v.x, wu.x);
                FFMA2(accU[c], v.y, wu.y);
                FFMA2(accV[c], v.x, wv.x);
                FFMA2(accV[c], v.y, wv.y);
            }
        }
    }

    int n = n0 + tid;
    if (n < n_nodes) {
        float* Pr = g_P + (size_t)n * PSTRIDE;
        float* Qr = g_Q + (size_t)n * PSTRIDE;
#pragma unroll
        for (int c = 0; c < N_CLASS; c++) {
            Pr[c] = unpack_sum(accU[c]) + bsh[c];
            Qr[c] = unpack_sum(accV[c]);
        }
        Pr[10] = 0.f; Pr[11] = 0.f;
        Qr[10] = 0.f; Qr[11] = 0.f;
    }
}

// ---------------------------------------------------------------------------
// Kernel 2: per-edge, staged + packed.
//   out[e] = edge_h[e] @ W[:,256:384]^T + P[src[e]] + Q[dst[e]]
// ---------------------------------------------------------------------------
__global__ void edge_score_kernel(const float* __restrict__ eh,
                                  const float* __restrict__ W,
                                  const int* __restrict__ src,
                                  const int* __restrict__ dst,
                                  float* __restrict__ out,
                                  int n_edges) {
    __shared__ float sW[N_CLASS * 128];
    __shared__ __align__(16) float sbuf[TILE * SROW];

    int tid = threadIdx.x;
    for (int i = tid; i < N_CLASS * 128; i += TILE) {
        int c = i >> 7, j = i & 127;
        sW[i] = W[c * 384 + 256 + j];
    }

    int e0 = blockIdx.x * TILE;
    bool full = (e0 + TILE <= n_edges);
    const float4* ehv = (const float4*)eh;

    unsigned long long acc[N_CLASS];
#pragma unroll
    for (int c = 0; c < N_CLASS; c++) acc[c] = 0ull;

    for (int chunk = 0; chunk < 4; chunk++) {
        __syncthreads();
#pragma unroll
        for (int k = 0; k < 8; k++) {
            int li = tid + k * TILE;
            int r = li >> 3, cc = li & 7;
            float4 v;
            if (full || (e0 + r) < n_edges)
                v = ehv[(size_t)(e0 + r) * 32 + chunk * 8 + cc];
            else
                v = make_float4(0.f, 0.f, 0.f, 0.f);
            *(float4*)(sbuf + r * SROW + cc * 4) = v;
        }
        __syncthreads();

        const ulonglong2* vt = (const ulonglong2*)(sbuf + tid * SROW);
        const ulonglong2* Wp = (const ulonglong2*)sW;
#pragma unroll
        for (int i = 0; i < 8; i++) {
            ulonglong2 v = vt[i];
#pragma unroll
            for (int c = 0; c < N_CLASS; c++) {
                ulonglong2 w = Wp[c * 32 + chunk * 8 + i];
                FFMA2(acc[c], v.x, w.x);
                FFMA2(acc[c], v.y, w.y);
            }
        }
    }

    int e = e0 + tid;
    if (e < n_edges) {
        int s = src[e];
        int d = dst[e];
        const float4* Pr = (const float4*)(g_P + (size_t)s * PSTRIDE);
        const float4* Qr = (const float4*)(g_Q + (size_t)d * PSTRIDE);
        float4 p0 = Pr[0], p1 = Pr[1], p2 = Pr[2];
        float4 q0 = Qr[0], q1 = Qr[1], q2 = Qr[2];

        float r0 = unpack_sum(acc[0]) + p0.x + q0.x;
        float r1 = unpack_sum(acc[1]) + p0.y + q0.y;
        float r2 = unpack_sum(acc[2]) + p0.z + q0.z;
        float r3 = unpack_sum(acc[3]) + p0.w + q0.w;
        float r4 = unpack_sum(acc[4]) + p1.x + q1.x;
        float r5 = unpack_sum(acc[5]) + p1.y + q1.y;
        float r6 = unpack_sum(acc[6]) + p1.z + q1.z;
        float r7 = unpack_sum(acc[7]) + p1.w + q1.w;
        float r8 = unpack_sum(acc[8]) + p2.x + q2.x;
        float r9 = unpack_sum(acc[9]) + p2.y + q2.y;

        float2* o2 = (float2*)(out + (size_t)e * N_CLASS);
        o2[0] = make_float2(r0, r1);
        o2[1] = make_float2(r2, r3);
        o2[2] = make_float2(r4, r5);
        o2[3] = make_float2(r6, r7);
        o2[4] = make_float2(r8, r9);
    }
}

// ---------------------------------------------------------------------------
extern "C" void kernel_launch(void* const* d_in, const int* in_sizes, int n_in,
                              void* d_out, int out_size) {
    const float* h   = (const float*)d_in[0];
    const float* eh  = (const float*)d_in[1];
    const float* W   = (const float*)d_in[2];
    const float* b   = (const float*)d_in[3];
    const int*   src = (const int*)d_in[4];
    const int*   dst = (const int*)d_in[5];
    float*       out = (float*)d_out;

    int n_nodes = in_sizes[0] / D_FEAT;
    int n_edges = in_sizes[4];

    node_project_kernel<<<(n_nodes + TILE - 1) / TILE, TILE>>>(h, W, b, n_nodes);
    edge_score_kernel<<<(n_edges + TILE - 1) / TILE, TILE>>>(eh, W, src, dst, out, n_edges);
}